// round 5
// baseline (speedup 1.0000x reference)
#include <cuda_runtime.h>
#include <cuda_bf16.h>
#include <cstdint>

#define B_TOT    16384
#define TSTEPS   40
#define ZSTR     304                       // bytes/row: 144 bf16 cols + pad (76 words, conflict-free)
#define ZBUF_SZ  (128*ZSTR)                // 38912
#define PLANE_SZ (128*ZSTR)
#define OFF_ZBUF 0                         // 2 buffers (A operand: [z(128) | xs(8) | pad])
#define OFF_WPL  (2*ZBUF_SZ)               // 3 weight split planes [n=128][k=144]
#define OFF_PBUF (OFF_WPL + 3*PLANE_SZ)    // readout partials [2][8][128][2] f32
#define PBUF_HALF (8*128*8)
#define OFF_ZOCC (OFF_PBUF + 2*PBUF_HALF)  // occupancy bytes [2][2][8]
#define SMEM_BYTES (OFF_ZOCC + 64)         // 211008 B

__device__ __forceinline__ uint32_t s2u(const void* p) {
    uint32_t a;
    asm("{ .reg .u64 t; cvta.to.shared.u64 t, %1; cvt.u32.u64 %0, t; }" : "=r"(a) : "l"(p));
    return a;
}

__device__ __forceinline__ void ldsm4(uint32_t* r, uint32_t addr) {
    asm volatile("ldmatrix.sync.aligned.m8n8.x4.shared.b16 {%0,%1,%2,%3}, [%4];"
        : "=r"(r[0]), "=r"(r[1]), "=r"(r[2]), "=r"(r[3]) : "r"(addr));
}

__device__ __forceinline__ void mma_bf(float* d, const uint32_t* a, uint32_t b0, uint32_t b1) {
    asm volatile("mma.sync.aligned.m16n8k16.row.col.f32.bf16.bf16.f32 "
        "{%0,%1,%2,%3}, {%4,%5,%6,%7}, {%8,%9}, {%0,%1,%2,%3};"
        : "+f"(d[0]), "+f"(d[1]), "+f"(d[2]), "+f"(d[3])
        : "r"(a[0]), "r"(a[1]), "r"(a[2]), "r"(a[3]), "r"(b0), "r"(b1));
}

__global__ void __launch_bounds__(512, 1) snn_hmma_kernel(
    const float* __restrict__ x,      // (B,4)
    const float* __restrict__ w_in,   // (128,8)
    const float* __restrict__ w_rec,  // (128,128)
    const float* __restrict__ w_out,  // (2,128)
    const float* __restrict__ mask,   // (T,B,128)
    float* __restrict__ out)          // (B,2)
{
    extern __shared__ char smem[];
    const uint32_t sb = s2u(smem);
    const int tid  = threadIdx.x;
    const int lane = tid & 31, wid = tid >> 5;
    const int mg = wid & 1;            // M group: rows 64*mg
    const int ng = wid >> 1;           // N group: cols 16*ng
    const int q  = lane & 3;
    const int rA = lane >> 2;          // 0..7
    const int rowBase = mg * 64 + rA;  // + mt*16 + rh*8
    const int colBase = ng * 16 + 2 * q;
    const int bgBase  = blockIdx.x * 128;

    // ---------------- init: zero z buffers + occupancy ----------------
    for (int i = tid; i < 2 * ZBUF_SZ / 4; i += 512)
        ((uint32_t*)(smem + OFF_ZBUF))[i] = 0u;
    if (tid < 32) smem[OFF_ZOCC + tid] = 0;

    // ---------------- init: build 3 bf16 split weight planes ----------------
    // plane[s][n][k]: k<128 -> w_rec[n][k]; 128<=k<136 -> w_in[n][k-128]; else 0
    for (int idx = tid; idx < 128 * 152; idx += 512) {
        int n = idx / 152, k = idx % 152;
        float wv = 0.f;
        if (k < 128)       wv = w_rec[n * 128 + k];
        else if (k < 136)  wv = w_in[n * 8 + (k - 128)];
        __nv_bfloat16 b0 = __float2bfloat16(wv);  float r1 = wv - __bfloat162float(b0);
        __nv_bfloat16 b1 = __float2bfloat16(r1);  float r2 = r1 - __bfloat162float(b1);
        __nv_bfloat16 b2 = __float2bfloat16(r2);
        uint32_t o = (uint32_t)(n * ZSTR + k * 2);
        *(__nv_bfloat16*)(smem + OFF_WPL + o)              = b0;
        *(__nv_bfloat16*)(smem + OFF_WPL + PLANE_SZ + o)   = b1;
        *(__nv_bfloat16*)(smem + OFF_WPL + 2*PLANE_SZ + o) = b2;
    }

    // readout weights for my 4 columns (2 n-tiles x 2 halves)
    float wo[2][2][2];
#pragma unroll
    for (int o = 0; o < 2; o++)
#pragma unroll
        for (int nt = 0; nt < 2; nt++)
#pragma unroll
            for (int hf = 0; hf < 2; hf++)
                wo[o][nt][hf] = w_out[o * 128 + colBase + nt * 8 + hf];

    // encoder: thread owns batch bl, channels 2*qe, 2*qe+1
    const int bl = tid >> 2;
    const int qe = tid & 3;
    const float esgn = (qe < 2) ? 50.f : -50.f;
    const int   exc  = (qe & 1) * 2;
    float cur0 = fmaxf(esgn * x[(bgBase + bl) * 4 + exc],     0.f);
    float cur1 = fmaxf(esgn * x[(bgBase + bl) * 4 + exc + 1], 0.f);
    float e0 = 0.f, e1 = 0.f;

    __syncthreads();   // zbuf zeroed before encoder writes into it

    // pre-loop: xs_0 into zbuf[0]
    {
        float en0 = e0 + 0.1f * (cur0 - e0); bool s0 = en0 > 1.f; e0 = s0 ? 0.f : en0;
        float en1 = e1 + 0.1f * (cur1 - e1); bool s1 = en1 > 1.f; e1 = s1 ? 0.f : en1;
        uint32_t wv = (s0 ? 0x3F80u : 0u) | (s1 ? 0x3F800000u : 0u);
        asm volatile("st.shared.b32 [%0], %1;"
            :: "r"(sb + OFF_ZBUF + (uint32_t)(bl * ZSTR + 256 + qe * 4)), "r"(wv));
    }
    __syncthreads();

    // ldmatrix lane addressing (A: row-major 16x16; B: two n8-tiles x k16)
    const uint32_t aLane = (uint32_t)((lane & 15) * ZSTR + (lane >> 4) * 16);
    const uint32_t aBase = sb + OFF_ZBUF + (uint32_t)(mg * 64) * ZSTR + aLane;
    const uint32_t bLane = (uint32_t)((((lane >> 4) & 1) * 8 + (lane & 7)) * ZSTR
                                      + ((lane >> 3) & 1) * 16);
    const uint32_t bBase = sb + OFF_WPL + (uint32_t)(ng * 16) * ZSTR + bLane;

    // state
    float v[4][2][4], c[4][2][4];
#pragma unroll
    for (int mt = 0; mt < 4; mt++)
#pragma unroll
        for (int nt = 0; nt < 2; nt++)
#pragma unroll
            for (int d = 0; d < 4; d++) { v[mt][nt][d] = 0.f; c[mt][nt][d] = 0.f; }
    float VO0 = 0.f, VO1 = 0.f, IO0 = 0.f, IO1 = 0.f;
    float M0 = 0.f, M1 = 0.f;    // recorded_0 == 0 always

#pragma unroll 1
    for (int t = 0; t < TSTEPS; t++) {
        const int par = t & 1, parW = par ^ 1;

        // (1) LI readout update with p_{t-1}
        if (t > 0 && tid < 128) {
            const char* pb = smem + OFF_PBUF + (size_t)(par ^ 1) * PBUF_HALF;
            float s0 = 0.f, s1 = 0.f;
#pragma unroll
            for (int g = 0; g < 8; g++) {
                float2 pv = *(const float2*)(pb + (g * 128 + tid) * 8);
                s0 += pv.x; s1 += pv.y;
            }
            IO0 = IO0 * 0.8f + s0;
            IO1 = IO1 * 0.8f + s1;
            VO0 = VO0 + 0.1f * (IO0 - VO0);
            VO1 = VO1 + 0.1f * (IO1 - VO1);
            M0 = fmaxf(M0, VO0); M1 = fmaxf(M1, VO1);
        }

        // (2) membrane update, spikes z_t (from c BEFORE decay/drive)
        uint32_t zm = 0;
#pragma unroll
        for (int mt = 0; mt < 4; mt++)
#pragma unroll
            for (int nt = 0; nt < 2; nt++)
#pragma unroll
                for (int d = 0; d < 4; d++) {
                    float vd = v[mt][nt][d] + 0.1f * (c[mt][nt][d] - v[mt][nt][d]);
                    bool z = vd > 1.f;
                    zm |= z ? (1u << (mt * 8 + nt * 4 + d)) : 0u;
                    v[mt][nt][d] = z ? 0.f : vd;
                }

        // (3) write z_t (bf16) into zbuf[parW]; occupancy byte
        {
            uint32_t zwBase = sb + OFF_ZBUF + (uint32_t)parW * ZBUF_SZ
                            + (uint32_t)(rowBase * ZSTR + colBase * 2);
#pragma unroll
            for (int mt = 0; mt < 4; mt++)
#pragma unroll
                for (int nt = 0; nt < 2; nt++)
#pragma unroll
                    for (int rh = 0; rh < 2; rh++) {
                        uint32_t bb = (zm >> (mt * 8 + nt * 4 + rh * 2)) & 3u;
                        uint32_t wv = ((bb & 1u) ? 0x3F80u : 0u) | ((bb & 2u) ? 0x3F800000u : 0u);
                        asm volatile("st.shared.b32 [%0], %1;"
                            :: "r"(zwBase + (uint32_t)((mt * 16 + rh * 8) * ZSTR + nt * 16)), "r"(wv));
                    }
            bool any = __any_sync(0xffffffffu, zm != 0u);
            if (lane == 0)
                smem[OFF_ZOCC + parW * 16 + mg * 8 + ng] = any ? 1 : 0;
        }

        // (4) c *= 0.8, then MMA-accumulate drive_t = [z_{t-1}|xs_t] @ planes
#pragma unroll
        for (int mt = 0; mt < 4; mt++)
#pragma unroll
            for (int nt = 0; nt < 2; nt++)
#pragma unroll
                for (int d = 0; d < 4; d++) c[mt][nt][d] *= 0.8f;

        {
            const uint64_t occ = *(const uint64_t*)(smem + OFF_ZOCC + par * 16 + mg * 8);
            const uint32_t aB = aBase + (uint32_t)par * ZBUF_SZ;
#pragma unroll
            for (int kt = 0; kt < 9; kt++) {
                bool run = (kt == 8) || (((occ >> (kt * 8)) & 0xffull) != 0ull);
                if (run) {
                    uint32_t a[4][4];
#pragma unroll
                    for (int mt = 0; mt < 4; mt++)
                        ldsm4(a[mt], aB + (uint32_t)(mt * 16 * ZSTR + kt * 32));
#pragma unroll
                    for (int s = 0; s < 3; s++) {
                        uint32_t b[4];
                        ldsm4(b, bBase + (uint32_t)(s * PLANE_SZ + kt * 32));
#pragma unroll
                        for (int mt = 0; mt < 4; mt++) {
                            mma_bf(c[mt][0], a[mt], b[0], b[1]);
                            mma_bf(c[mt][1], a[mt], b[2], b[3]);
                        }
                    }
                }
            }
        }

        // (5) dropout + readout partials p_t -> pbuf[par]
        {
            float pp[8][2];
#pragma unroll
            for (int i = 0; i < 8; i++) { pp[i][0] = 0.f; pp[i][1] = 0.f; }
            if (zm) {
                const float* mt_ptr = mask + (size_t)t * (B_TOT * 128)
                                    + (size_t)(bgBase + rowBase) * 128 + colBase;
#pragma unroll
                for (int mt = 0; mt < 4; mt++)
#pragma unroll
                    for (int rh = 0; rh < 2; rh++)
#pragma unroll
                        for (int nt = 0; nt < 2; nt++) {
                            uint32_t bb = (zm >> (mt * 8 + nt * 4 + rh * 2)) & 3u;
                            if (bb) {
                                float2 mv = *(const float2*)(mt_ptr + (mt * 16 + rh * 8) * 128 + nt * 8);
                                if (bb & 1u) { pp[mt*2+rh][0] += mv.x * wo[0][nt][0];
                                               pp[mt*2+rh][1] += mv.x * wo[1][nt][0]; }
                                if (bb & 2u) { pp[mt*2+rh][0] += mv.y * wo[0][nt][1];
                                               pp[mt*2+rh][1] += mv.y * wo[1][nt][1]; }
                            }
                        }
            }
#pragma unroll
            for (int i = 0; i < 8; i++) {
                pp[i][0] += __shfl_xor_sync(0xffffffffu, pp[i][0], 1);
                pp[i][0] += __shfl_xor_sync(0xffffffffu, pp[i][0], 2);
                pp[i][1] += __shfl_xor_sync(0xffffffffu, pp[i][1], 1);
                pp[i][1] += __shfl_xor_sync(0xffffffffu, pp[i][1], 2);
            }
            if (q == 0) {
                char* pb = smem + OFF_PBUF + (size_t)par * PBUF_HALF;
#pragma unroll
                for (int mt = 0; mt < 4; mt++)
#pragma unroll
                    for (int rh = 0; rh < 2; rh++) {
                        int row = rowBase + mt * 16 + rh * 8;
                        *(float2*)(pb + (ng * 128 + row) * 8)
                            = make_float2(pp[mt*2+rh][0], pp[mt*2+rh][1]);
                    }
            }
        }

        // (6) encoder advance -> xs_{t+1} into zbuf[parW]
        {
            float en0 = e0 + 0.1f * (cur0 - e0); bool s0 = en0 > 1.f; e0 = s0 ? 0.f : en0;
            float en1 = e1 + 0.1f * (cur1 - e1); bool s1 = en1 > 1.f; e1 = s1 ? 0.f : en1;
            uint32_t wv = (s0 ? 0x3F80u : 0u) | (s1 ? 0x3F800000u : 0u);
            asm volatile("st.shared.b32 [%0], %1;"
                :: "r"(sb + OFF_ZBUF + (uint32_t)parW * ZBUF_SZ
                       + (uint32_t)(bl * ZSTR + 256 + qe * 4)), "r"(wv));
        }

        __syncthreads();
    }

    // final: softmax over max voltages
    if (tid < 128) {
        float mx = fmaxf(M0, M1);
        float ex0 = expf(M0 - mx), ex1 = expf(M1 - mx);
        float s = ex0 + ex1;
        out[(size_t)(bgBase + tid) * 2 + 0] = ex0 / s;
        out[(size_t)(bgBase + tid) * 2 + 1] = ex1 / s;
    }
}

extern "C" void kernel_launch(void* const* d_in, const int* in_sizes, int n_in,
                              void* d_out, int out_size)
{
    const float* x     = (const float*)d_in[0];
    const float* w_in  = (const float*)d_in[1];
    const float* w_rec = (const float*)d_in[2];
    const float* w_out = (const float*)d_in[3];
    const float* mask  = (const float*)d_in[4];
    float* out = (float*)d_out;

    cudaFuncSetAttribute(snn_hmma_kernel,
                         cudaFuncAttributeMaxDynamicSharedMemorySize, SMEM_BYTES);

    snn_hmma_kernel<<<B_TOT / 128, 512, SMEM_BYTES>>>(x, w_in, w_rec, w_out, mask, out);
}

// round 6
// speedup vs baseline: 1.1838x; 1.1838x over previous
#include <cuda_runtime.h>
#include <cuda_bf16.h>
#include <cstdint>

#define B_TOT    16384
#define TSTEPS   40
#define ZSTR     304                       // bytes/row: 144 bf16 cols + pad (76 words, conflict-free)
#define ZBUF_SZ  (128*ZSTR)                // 38912
#define PLANE_SZ (128*ZSTR)
#define OFF_ZBUF 0                         // 2 buffers (A operand: [z(128) | xs(8) | pad])
#define OFF_WPL  (2*ZBUF_SZ)               // 3 weight split planes [n=128][k=144]
#define OFF_PBUF (OFF_WPL + 3*PLANE_SZ)    // readout partials [2][8][128][2] f32
#define PBUF_HALF (8*128*8)
#define OFF_ZOCC (OFF_PBUF + 2*PBUF_HALF)  // occupancy bytes [2][2][8]
#define SMEM_BYTES (OFF_ZOCC + 64)         // 211008 B

__device__ __forceinline__ uint32_t s2u(const void* p) {
    uint32_t a;
    asm("{ .reg .u64 t; cvta.to.shared.u64 t, %1; cvt.u32.u64 %0, t; }" : "=r"(a) : "l"(p));
    return a;
}

__device__ __forceinline__ void ldsm4(uint32_t* r, uint32_t addr) {
    asm volatile("ldmatrix.sync.aligned.m8n8.x4.shared.b16 {%0,%1,%2,%3}, [%4];"
        : "=r"(r[0]), "=r"(r[1]), "=r"(r[2]), "=r"(r[3]) : "r"(addr));
}

__device__ __forceinline__ void mma_bf(float* d, const uint32_t* a, uint32_t b0, uint32_t b1) {
    asm volatile("mma.sync.aligned.m16n8k16.row.col.f32.bf16.bf16.f32 "
        "{%0,%1,%2,%3}, {%4,%5,%6,%7}, {%8,%9}, {%0,%1,%2,%3};"
        : "+f"(d[0]), "+f"(d[1]), "+f"(d[2]), "+f"(d[3])
        : "r"(a[0]), "r"(a[1]), "r"(a[2]), "r"(a[3]), "r"(b0), "r"(b1));
}

__global__ void __launch_bounds__(512, 1) snn_hmma_kernel(
    const float* __restrict__ x,      // (B,4)
    const float* __restrict__ w_in,   // (128,8)
    const float* __restrict__ w_rec,  // (128,128)
    const float* __restrict__ w_out,  // (2,128)
    const float* __restrict__ mask,   // (T,B,128)
    float* __restrict__ out)          // (B,2)
{
    extern __shared__ char smem[];
    const uint32_t sb = s2u(smem);
    const int tid  = threadIdx.x;
    const int lane = tid & 31, wid = tid >> 5;
    const int mg = wid & 1;            // M group: rows 64*mg
    const int ng = wid >> 1;           // N group: cols 16*ng
    const int q  = lane & 3;
    const int rA = lane >> 2;          // 0..7
    const int rowBase = mg * 64 + rA;  // + mt*16 + rh*8
    const int colBase = ng * 16 + 2 * q;
    const int bgBase  = blockIdx.x * 128;

    // ---------------- init: zero z buffers + occupancy ----------------
    for (int i = tid; i < 2 * ZBUF_SZ / 4; i += 512)
        ((uint32_t*)(smem + OFF_ZBUF))[i] = 0u;
    if (tid < 32) smem[OFF_ZOCC + tid] = 0;

    // ---------------- init: build 3 bf16 split weight planes ----------------
    // plane[s][n][k]: k<128 -> w_rec[n][k]; 128<=k<136 -> w_in[n][k-128]; else 0
    for (int idx = tid; idx < 128 * 152; idx += 512) {
        int n = idx / 152, k = idx % 152;
        float wv = 0.f;
        if (k < 128)       wv = w_rec[n * 128 + k];
        else if (k < 136)  wv = w_in[n * 8 + (k - 128)];
        __nv_bfloat16 b0 = __float2bfloat16(wv);  float r1 = wv - __bfloat162float(b0);
        __nv_bfloat16 b1 = __float2bfloat16(r1);  float r2 = r1 - __bfloat162float(b1);
        __nv_bfloat16 b2 = __float2bfloat16(r2);
        uint32_t o = (uint32_t)(n * ZSTR + k * 2);
        *(__nv_bfloat16*)(smem + OFF_WPL + o)              = b0;
        *(__nv_bfloat16*)(smem + OFF_WPL + PLANE_SZ + o)   = b1;
        *(__nv_bfloat16*)(smem + OFF_WPL + 2*PLANE_SZ + o) = b2;
    }

    // readout weights for my 4 columns (2 n-tiles x 2 halves)
    float wo[2][2][2];
#pragma unroll
    for (int o = 0; o < 2; o++)
#pragma unroll
        for (int nt = 0; nt < 2; nt++)
#pragma unroll
            for (int hf = 0; hf < 2; hf++)
                wo[o][nt][hf] = w_out[o * 128 + colBase + nt * 8 + hf];

    // encoder: thread owns batch bl, channels 2*qe, 2*qe+1
    const int bl = tid >> 2;
    const int qe = tid & 3;
    const float esgn = (qe < 2) ? 50.f : -50.f;
    const int   exc  = (qe & 1) * 2;
    float cur0 = fmaxf(esgn * x[(bgBase + bl) * 4 + exc],     0.f);
    float cur1 = fmaxf(esgn * x[(bgBase + bl) * 4 + exc + 1], 0.f);
    float e0 = 0.f, e1 = 0.f;

    __syncthreads();   // zbuf zeroed before encoder writes into it

    // pre-loop: xs_0 into zbuf[0]
    {
        float en0 = e0 + 0.1f * (cur0 - e0); bool s0 = en0 > 1.f; e0 = s0 ? 0.f : en0;
        float en1 = e1 + 0.1f * (cur1 - e1); bool s1 = en1 > 1.f; e1 = s1 ? 0.f : en1;
        uint32_t wv = (s0 ? 0x3F80u : 0u) | (s1 ? 0x3F800000u : 0u);
        asm volatile("st.shared.b32 [%0], %1;"
            :: "r"(sb + OFF_ZBUF + (uint32_t)(bl * ZSTR + 256 + qe * 4)), "r"(wv));
    }
    __syncthreads();

    // ldmatrix lane addressing (A: row-major 16x16; B: two n8-tiles x k16)
    const uint32_t aLane = (uint32_t)((lane & 15) * ZSTR + (lane >> 4) * 16);
    const uint32_t aBase = sb + OFF_ZBUF + (uint32_t)(mg * 64) * ZSTR + aLane;
    const uint32_t bLane = (uint32_t)((((lane >> 4) & 1) * 8 + (lane & 7)) * ZSTR
                                      + ((lane >> 3) & 1) * 16);
    const uint32_t bBase = sb + OFF_WPL + (uint32_t)(ng * 16) * ZSTR + bLane;

    // state
    float v[4][2][4], c[4][2][4];
#pragma unroll
    for (int mt = 0; mt < 4; mt++)
#pragma unroll
        for (int nt = 0; nt < 2; nt++)
#pragma unroll
            for (int d = 0; d < 4; d++) { v[mt][nt][d] = 0.f; c[mt][nt][d] = 0.f; }
    float VO0 = 0.f, VO1 = 0.f, IO0 = 0.f, IO1 = 0.f;
    float M0 = 0.f, M1 = 0.f;    // recorded_0 == 0 always

#pragma unroll 1
    for (int t = 0; t < TSTEPS; t++) {
        const int par = t & 1, parW = par ^ 1;

        // (1) LI readout update with p_{t-1}
        if (t > 0 && tid < 128) {
            const char* pb = smem + OFF_PBUF + (size_t)(par ^ 1) * PBUF_HALF;
            float s0 = 0.f, s1 = 0.f;
#pragma unroll
            for (int g = 0; g < 8; g++) {
                float2 pv = *(const float2*)(pb + (g * 128 + tid) * 8);
                s0 += pv.x; s1 += pv.y;
            }
            IO0 = IO0 * 0.8f + s0;
            IO1 = IO1 * 0.8f + s1;
            VO0 = VO0 + 0.1f * (IO0 - VO0);
            VO1 = VO1 + 0.1f * (IO1 - VO1);
            M0 = fmaxf(M0, VO0); M1 = fmaxf(M1, VO1);
        }

        // (2) membrane update, spikes z_t (from c BEFORE decay/drive)
        uint32_t zm = 0;
#pragma unroll
        for (int mt = 0; mt < 4; mt++)
#pragma unroll
            for (int nt = 0; nt < 2; nt++)
#pragma unroll
                for (int d = 0; d < 4; d++) {
                    float vd = v[mt][nt][d] + 0.1f * (c[mt][nt][d] - v[mt][nt][d]);
                    bool z = vd > 1.f;
                    zm |= z ? (1u << (mt * 8 + nt * 4 + d)) : 0u;
                    v[mt][nt][d] = z ? 0.f : vd;
                }

        // (3) write z_t (bf16) into zbuf[parW]; occupancy byte; prefetch mask lines
        const float* mt_ptr = mask + (size_t)t * (B_TOT * 128)
                            + (size_t)(bgBase + rowBase) * 128 + colBase;
        {
            uint32_t zwBase = sb + OFF_ZBUF + (uint32_t)parW * ZBUF_SZ
                            + (uint32_t)(rowBase * ZSTR + colBase * 2);
#pragma unroll
            for (int mt = 0; mt < 4; mt++)
#pragma unroll
                for (int nt = 0; nt < 2; nt++)
#pragma unroll
                    for (int rh = 0; rh < 2; rh++) {
                        uint32_t bb = (zm >> (mt * 8 + nt * 4 + rh * 2)) & 3u;
                        uint32_t wv = ((bb & 1u) ? 0x3F80u : 0u) | ((bb & 2u) ? 0x3F800000u : 0u);
                        asm volatile("st.shared.b32 [%0], %1;"
                            :: "r"(zwBase + (uint32_t)((mt * 16 + rh * 8) * ZSTR + nt * 16)), "r"(wv));
                    }
            bool any = __any_sync(0xffffffffu, zm != 0u);
            if (lane == 0)
                smem[OFF_ZOCC + parW * 16 + mg * 8 + ng] = any ? 1 : 0;

            // prefetch mask rows we'll need in (5): hides DRAM->L2 behind the MMAs
            if (zm) {
#pragma unroll
                for (int mt = 0; mt < 4; mt++)
#pragma unroll
                    for (int rh = 0; rh < 2; rh++) {
                        uint32_t rb = (zm >> (mt * 8 + rh * 2));
                        if ((rb & 3u) || ((rb >> 4) & 3u)) {
                            const float* pa = mt_ptr + (mt * 16 + rh * 8) * 128;
                            asm volatile("prefetch.global.L2 [%0];" :: "l"(pa));
                            asm volatile("prefetch.global.L2 [%0];" :: "l"(pa + 8));
                        }
                    }
            }
        }

        // (4) c *= 0.8, then MMA-accumulate drive_t = [z_{t-1}|xs_t] @ planes
#pragma unroll
        for (int mt = 0; mt < 4; mt++)
#pragma unroll
            for (int nt = 0; nt < 2; nt++)
#pragma unroll
                for (int d = 0; d < 4; d++) c[mt][nt][d] *= 0.8f;

        {
            const uint64_t occ = *(const uint64_t*)(smem + OFF_ZOCC + par * 16 + mg * 8);
            const uint32_t aB = aBase + (uint32_t)par * ZBUF_SZ;
            if (occ != 0ull) {              // any z spikes last step: run kt 0..7
#pragma unroll
                for (int kt = 0; kt < 8; kt++) {
                    uint32_t a[4][4];
#pragma unroll
                    for (int mt = 0; mt < 4; mt++)
                        ldsm4(a[mt], aB + (uint32_t)(mt * 16 * ZSTR + kt * 32));
#pragma unroll
                    for (int s = 0; s < 3; s++) {
                        uint32_t b[4];
                        ldsm4(b, bBase + (uint32_t)(s * PLANE_SZ + kt * 32));
#pragma unroll
                        for (int mt = 0; mt < 4; mt++) {
                            mma_bf(c[mt][0], a[mt], b[0], b[1]);
                            mma_bf(c[mt][1], a[mt], b[2], b[3]);
                        }
                    }
                }
            }
            {   // kt=8: encoder columns, always
                uint32_t a[4][4];
#pragma unroll
                for (int mt = 0; mt < 4; mt++)
                    ldsm4(a[mt], aB + (uint32_t)(mt * 16 * ZSTR + 8 * 32));
#pragma unroll
                for (int s = 0; s < 3; s++) {
                    uint32_t b[4];
                    ldsm4(b, bBase + (uint32_t)(s * PLANE_SZ + 8 * 32));
#pragma unroll
                    for (int mt = 0; mt < 4; mt++) {
                        mma_bf(c[mt][0], a[mt], b[0], b[1]);
                        mma_bf(c[mt][1], a[mt], b[2], b[3]);
                    }
                }
            }
        }

        // (5) dropout + readout partials p_t -> pbuf[par]  (mask now L2-hot)
        {
            char* pb = smem + OFF_PBUF + (size_t)par * PBUF_HALF;
#pragma unroll
            for (int mt = 0; mt < 4; mt++) {
                float pr[2][2];
                pr[0][0] = pr[0][1] = pr[1][0] = pr[1][1] = 0.f;
                uint32_t mtb = (zm >> (mt * 8)) & 0xFFu;
                if (mtb) {
#pragma unroll
                    for (int rh = 0; rh < 2; rh++)
#pragma unroll
                        for (int nt = 0; nt < 2; nt++) {
                            uint32_t bb = (mtb >> (nt * 4 + rh * 2)) & 3u;
                            if (bb) {
                                float2 mv = *(const float2*)(mt_ptr + (mt * 16 + rh * 8) * 128 + nt * 8);
                                if (bb & 1u) { pr[rh][0] += mv.x * wo[0][nt][0];
                                               pr[rh][1] += mv.x * wo[1][nt][0]; }
                                if (bb & 2u) { pr[rh][0] += mv.y * wo[0][nt][1];
                                               pr[rh][1] += mv.y * wo[1][nt][1]; }
                            }
                        }
                }
#pragma unroll
                for (int rh = 0; rh < 2; rh++) {
                    pr[rh][0] += __shfl_xor_sync(0xffffffffu, pr[rh][0], 1);
                    pr[rh][0] += __shfl_xor_sync(0xffffffffu, pr[rh][0], 2);
                    pr[rh][1] += __shfl_xor_sync(0xffffffffu, pr[rh][1], 1);
                    pr[rh][1] += __shfl_xor_sync(0xffffffffu, pr[rh][1], 2);
                }
                if (q == 0) {
#pragma unroll
                    for (int rh = 0; rh < 2; rh++) {
                        int row = rowBase + mt * 16 + rh * 8;
                        *(float2*)(pb + (ng * 128 + row) * 8)
                            = make_float2(pr[rh][0], pr[rh][1]);
                    }
                }
            }
        }

        // (6) encoder advance -> xs_{t+1} into zbuf[parW]
        {
            float en0 = e0 + 0.1f * (cur0 - e0); bool s0 = en0 > 1.f; e0 = s0 ? 0.f : en0;
            float en1 = e1 + 0.1f * (cur1 - e1); bool s1 = en1 > 1.f; e1 = s1 ? 0.f : en1;
            uint32_t wv = (s0 ? 0x3F80u : 0u) | (s1 ? 0x3F800000u : 0u);
            asm volatile("st.shared.b32 [%0], %1;"
                :: "r"(sb + OFF_ZBUF + (uint32_t)parW * ZBUF_SZ
                       + (uint32_t)(bl * ZSTR + 256 + qe * 4)), "r"(wv));
        }

        __syncthreads();
    }

    // final: softmax over max voltages
    if (tid < 128) {
        float mx = fmaxf(M0, M1);
        float ex0 = expf(M0 - mx), ex1 = expf(M1 - mx);
        float s = ex0 + ex1;
        out[(size_t)(bgBase + tid) * 2 + 0] = ex0 / s;
        out[(size_t)(bgBase + tid) * 2 + 1] = ex1 / s;
    }
}

extern "C" void kernel_launch(void* const* d_in, const int* in_sizes, int n_in,
                              void* d_out, int out_size)
{
    const float* x     = (const float*)d_in[0];
    const float* w_in  = (const float*)d_in[1];
    const float* w_rec = (const float*)d_in[2];
    const float* w_out = (const float*)d_in[3];
    const float* mask  = (const float*)d_in[4];
    float* out = (float*)d_out;

    cudaFuncSetAttribute(snn_hmma_kernel,
                         cudaFuncAttributeMaxDynamicSharedMemorySize, SMEM_BYTES);

    snn_hmma_kernel<<<B_TOT / 128, 512, SMEM_BYTES>>>(x, w_in, w_rec, w_out, mask, out);
}

// round 7
// speedup vs baseline: 1.2047x; 1.0177x over previous
#include <cuda_runtime.h>
#include <cuda_bf16.h>
#include <cstdint>

#define B_TOT    16384
#define TSTEPS   40
#define ZSTR     304                       // bytes/row: 144 bf16 cols + pad (76 words, conflict-free)
#define ZBUF_SZ  (128*ZSTR)                // 38912
#define PLANE_SZ (128*ZSTR)
#define OFF_ZBUF 0                         // 2 buffers (A operand: [z(128) | xs(8) | pad])
#define OFF_WPL  (2*ZBUF_SZ)               // 3 weight split planes [n=128][k=144]
#define OFF_PBUF (OFF_WPL + 3*PLANE_SZ)    // partials [par][half][ng8][64] float2 = 16 KB
#define OFF_WOP  (OFF_PBUF + 16384)        // w_out interleaved pairs: 128 float2 = 1 KB
#define OFF_ZOCC (OFF_WOP + 1024)          // occupancy bytes [par][half][8]
#define SMEM_BYTES (OFF_ZOCC + 64)

#define HBAR(hh) asm volatile("bar.sync %0, 256;" :: "r"((hh) + 1) : "memory")

__device__ __forceinline__ uint32_t s2u(const void* p) {
    uint32_t a;
    asm("{ .reg .u64 t; cvta.to.shared.u64 t, %1; cvt.u32.u64 %0, t; }" : "=r"(a) : "l"(p));
    return a;
}

__device__ __forceinline__ void ldsm4(uint32_t* r, uint32_t addr) {
    asm volatile("ldmatrix.sync.aligned.m8n8.x4.shared.b16 {%0,%1,%2,%3}, [%4];"
        : "=r"(r[0]), "=r"(r[1]), "=r"(r[2]), "=r"(r[3]) : "r"(addr));
}

__device__ __forceinline__ void mma_bf(float* d, const uint32_t* a, uint32_t b0, uint32_t b1) {
    asm volatile("mma.sync.aligned.m16n8k16.row.col.f32.bf16.bf16.f32 "
        "{%0,%1,%2,%3}, {%4,%5,%6,%7}, {%8,%9}, {%0,%1,%2,%3};"
        : "+f"(d[0]), "+f"(d[1]), "+f"(d[2]), "+f"(d[3])
        : "r"(a[0]), "r"(a[1]), "r"(a[2]), "r"(a[3]), "r"(b0), "r"(b1));
}

__global__ void __launch_bounds__(512, 1) snn_hmma_kernel(
    const float* __restrict__ x,      // (B,4)
    const float* __restrict__ w_in,   // (128,8)
    const float* __restrict__ w_rec,  // (128,128)
    const float* __restrict__ w_out,  // (2,128)
    const float* __restrict__ mask,   // (T,B,128)
    float* __restrict__ out)          // (B,2)
{
    extern __shared__ char smem[];
    const uint32_t sb = s2u(smem);
    const int tid  = threadIdx.x;
    const int lane = tid & 31, wid = tid >> 5;
    const int h  = wid >> 3;           // half: warps 0-7 -> batches 0-63, warps 8-15 -> 64-127
    const int ng = wid & 7;            // N group: cols 16*ng
    const int q  = lane & 3;
    const int rA = lane >> 2;          // 0..7
    const int rowL = rA;               // local row within half (+ mt*16 + rh*8)
    const int colBase = ng * 16 + 2 * q;
    const int bgBase  = blockIdx.x * 128;

    // ---------------- init ----------------
    for (int i = tid; i < 2 * ZBUF_SZ / 4; i += 512)
        ((uint32_t*)(smem + OFF_ZBUF))[i] = 0u;
    if (tid < 32) smem[OFF_ZOCC + tid] = 0;
    // w_out interleaved pairs
    if (tid < 128)
        *(float2*)(smem + OFF_WOP + tid * 8) = make_float2(w_out[tid], w_out[128 + tid]);

    // 3 bf16 split weight planes: plane[s][n][k]; k<128 w_rec, 128..135 w_in, else 0
    for (int idx = tid; idx < 128 * 152; idx += 512) {
        int n = idx / 152, k = idx % 152;
        float wv = 0.f;
        if (k < 128)       wv = w_rec[n * 128 + k];
        else if (k < 136)  wv = w_in[n * 8 + (k - 128)];
        __nv_bfloat16 b0 = __float2bfloat16(wv);  float r1 = wv - __bfloat162float(b0);
        __nv_bfloat16 b1 = __float2bfloat16(r1);  float r2 = r1 - __bfloat162float(b1);
        __nv_bfloat16 b2 = __float2bfloat16(r2);
        uint32_t o = (uint32_t)(n * ZSTR + k * 2);
        *(__nv_bfloat16*)(smem + OFF_WPL + o)              = b0;
        *(__nv_bfloat16*)(smem + OFF_WPL + PLANE_SZ + o)   = b1;
        *(__nv_bfloat16*)(smem + OFF_WPL + 2*PLANE_SZ + o) = b2;
    }

    // encoder: thread owns batch bl = tid>>2 (aligned with halves), channels 2 per thread
    const int bl = tid >> 2;
    const int qe = tid & 3;
    const float esgn = (qe < 2) ? 50.f : -50.f;
    const int   exc  = (qe & 1) * 2;
    float cur0 = fmaxf(esgn * x[(bgBase + bl) * 4 + exc],     0.f);
    float cur1 = fmaxf(esgn * x[(bgBase + bl) * 4 + exc + 1], 0.f);
    float e0 = 0.f, e1 = 0.f;

    __syncthreads();   // zbuf zeroed before encoder writes

    // pre-loop: xs_0 into zbuf[0]
    {
        float en0 = e0 + 0.1f * (cur0 - e0); bool s0 = en0 > 1.f; e0 = s0 ? 0.f : en0;
        float en1 = e1 + 0.1f * (cur1 - e1); bool s1 = en1 > 1.f; e1 = s1 ? 0.f : en1;
        uint32_t wv = (s0 ? 0x3F80u : 0u) | (s1 ? 0x3F800000u : 0u);
        asm volatile("st.shared.b32 [%0], %1;"
            :: "r"(sb + OFF_ZBUF + (uint32_t)(bl * ZSTR + 256 + qe * 4)), "r"(wv));
    }
    __syncthreads();

    // ldmatrix lane addressing
    const uint32_t aLane = (uint32_t)((lane & 15) * ZSTR + (lane >> 4) * 16);
    const uint32_t aBase = sb + OFF_ZBUF + (uint32_t)(h * 64) * ZSTR + aLane;
    const uint32_t bLane = (uint32_t)((((lane >> 4) & 1) * 8 + (lane & 7)) * ZSTR
                                      + ((lane >> 3) & 1) * 16);
    const uint32_t bBase = sb + OFF_WPL + (uint32_t)(ng * 16) * ZSTR + bLane;

    // state
    float v[4][2][4], c[4][2][4];
#pragma unroll
    for (int mt = 0; mt < 4; mt++)
#pragma unroll
        for (int nt = 0; nt < 2; nt++)
#pragma unroll
            for (int d = 0; d < 4; d++) { v[mt][nt][d] = 0.f; c[mt][nt][d] = 0.f; }
    float VO0 = 0.f, VO1 = 0.f, IO0 = 0.f, IO1 = 0.f;
    float M0 = 0.f, M1 = 0.f;

    // mask pointer for this warp's rows (incremented per step)
    const float* mrow = mask + (size_t)(bgBase + h * 64 + rowL) * 128 + colBase;
    const int r256 = tid & 255;          // index within half

#pragma unroll 1
    for (int t = 0; t < TSTEPS; t++) {
        const int par = t & 1, parW = par ^ 1;

        // (1) LI readout update with p_{t-1} (per half)
        if (t > 0 && r256 < 64) {
            const char* pb = smem + OFF_PBUF + (size_t)((par ^ 1) * 2 + h) * 4096;
            float s0 = 0.f, s1 = 0.f;
#pragma unroll
            for (int g = 0; g < 8; g++) {
                float2 pv = *(const float2*)(pb + (g * 64 + r256) * 8);
                s0 += pv.x; s1 += pv.y;
            }
            IO0 = IO0 * 0.8f + s0;
            IO1 = IO1 * 0.8f + s1;
            VO0 = VO0 + 0.1f * (IO0 - VO0);
            VO1 = VO1 + 0.1f * (IO1 - VO1);
            M0 = fmaxf(M0, VO0); M1 = fmaxf(M1, VO1);
        }

        // (2) membrane update, spikes z_t
        uint32_t zm = 0;
#pragma unroll
        for (int mt = 0; mt < 4; mt++)
#pragma unroll
            for (int nt = 0; nt < 2; nt++)
#pragma unroll
                for (int d = 0; d < 4; d++) {
                    float vd = v[mt][nt][d] + 0.1f * (c[mt][nt][d] - v[mt][nt][d]);
                    bool z = vd > 1.f;
                    zm |= z ? (1u << (mt * 8 + nt * 4 + d)) : 0u;
                    v[mt][nt][d] = z ? 0.f : vd;
                }

        // (3) write z_t -> zbuf[parW]; occupancy; L2 prefetch of needed mask lines
        {
            uint32_t zwBase = sb + OFF_ZBUF + (uint32_t)parW * ZBUF_SZ
                            + (uint32_t)((h * 64 + rowL) * ZSTR + colBase * 2);
#pragma unroll
            for (int mt = 0; mt < 4; mt++)
#pragma unroll
                for (int nt = 0; nt < 2; nt++)
#pragma unroll
                    for (int rh = 0; rh < 2; rh++) {
                        uint32_t bb = (zm >> (mt * 8 + nt * 4 + rh * 2)) & 3u;
                        uint32_t wv = ((bb & 1u) ? 0x3F80u : 0u) | ((bb & 2u) ? 0x3F800000u : 0u);
                        asm volatile("st.shared.b32 [%0], %1;"
                            :: "r"(zwBase + (uint32_t)((mt * 16 + rh * 8) * ZSTR + nt * 16)), "r"(wv));
                    }
            bool any = __any_sync(0xffffffffu, zm != 0u);
            if (lane == 0)
                smem[OFF_ZOCC + parW * 16 + h * 8 + ng] = any ? 1 : 0;

            if (zm) {
#pragma unroll
                for (int mt = 0; mt < 4; mt++)
#pragma unroll
                    for (int rh = 0; rh < 2; rh++) {
                        uint32_t rb = (zm >> (mt * 8 + rh * 2));
                        if ((rb & 3u) || ((rb >> 4) & 3u)) {
                            const float* pa = mrow + (mt * 16 + rh * 8) * 128;
                            asm volatile("prefetch.global.L2 [%0];" :: "l"(pa));
                            asm volatile("prefetch.global.L2 [%0];" :: "l"(pa + 8));
                        }
                    }
            }
        }

        // (4) c *= 0.8, MMA-accumulate drive
#pragma unroll
        for (int mt = 0; mt < 4; mt++)
#pragma unroll
            for (int nt = 0; nt < 2; nt++)
#pragma unroll
                for (int d = 0; d < 4; d++) c[mt][nt][d] *= 0.8f;

        {
            const uint64_t occ = *(const uint64_t*)(smem + OFF_ZOCC + par * 16 + h * 8);
            const uint32_t aB = aBase + (uint32_t)par * ZBUF_SZ;
            if (occ != 0ull) {
#pragma unroll
                for (int kt = 0; kt < 8; kt++) {
                    uint32_t a[4][4];
#pragma unroll
                    for (int mt = 0; mt < 4; mt++)
                        ldsm4(a[mt], aB + (uint32_t)(mt * 16 * ZSTR + kt * 32));
#pragma unroll
                    for (int s = 0; s < 3; s++) {
                        uint32_t b[4];
                        ldsm4(b, bBase + (uint32_t)(s * PLANE_SZ + kt * 32));
#pragma unroll
                        for (int mt = 0; mt < 4; mt++) {
                            mma_bf(c[mt][0], a[mt], b[0], b[1]);
                            mma_bf(c[mt][1], a[mt], b[2], b[3]);
                        }
                    }
                }
            }
            {   // kt=8: encoder columns, always
                uint32_t a[4][4];
#pragma unroll
                for (int mt = 0; mt < 4; mt++)
                    ldsm4(a[mt], aB + (uint32_t)(mt * 16 * ZSTR + 8 * 32));
#pragma unroll
                for (int s = 0; s < 3; s++) {
                    uint32_t b[4];
                    ldsm4(b, bBase + (uint32_t)(s * PLANE_SZ + 8 * 32));
#pragma unroll
                    for (int mt = 0; mt < 4; mt++) {
                        mma_bf(c[mt][0], a[mt], b[0], b[1]);
                        mma_bf(c[mt][1], a[mt], b[2], b[3]);
                    }
                }
            }
        }

        // (5) dropout + readout partials p_t -> pbuf[par][h][ng]
        {
            char* pb = smem + OFF_PBUF + (size_t)((par * 2 + h) * 8 + ng) * 512;
#pragma unroll
            for (int mt = 0; mt < 4; mt++)
#pragma unroll
                for (int rh = 0; rh < 2; rh++) {
                    float p0 = 0.f, p1 = 0.f;
                    uint32_t rb = zm >> (mt * 8 + rh * 2);
                    if ((rb & 3u) | ((rb >> 4) & 3u)) {
#pragma unroll
                        for (int nt = 0; nt < 2; nt++) {
                            uint32_t bb = (rb >> (nt * 4)) & 3u;
                            if (bb) {
                                float2 mv = *(const float2*)(mrow + (mt * 16 + rh * 8) * 128 + nt * 8);
                                float4 wp = *(const float4*)(smem + OFF_WOP + (colBase + nt * 8) * 8);
                                if (bb & 1u) { p0 += mv.x * wp.x; p1 += mv.x * wp.y; }
                                if (bb & 2u) { p0 += mv.y * wp.z; p1 += mv.y * wp.w; }
                            }
                        }
                    }
                    p0 += __shfl_xor_sync(0xffffffffu, p0, 1);
                    p0 += __shfl_xor_sync(0xffffffffu, p0, 2);
                    p1 += __shfl_xor_sync(0xffffffffu, p1, 1);
                    p1 += __shfl_xor_sync(0xffffffffu, p1, 2);
                    if (q == 0)
                        *(float2*)(pb + (rowL + mt * 16 + rh * 8) * 8) = make_float2(p0, p1);
                }
        }

        // (6) encoder advance -> xs_{t+1} into zbuf[parW]
        {
            float en0 = e0 + 0.1f * (cur0 - e0); bool s0 = en0 > 1.f; e0 = s0 ? 0.f : en0;
            float en1 = e1 + 0.1f * (cur1 - e1); bool s1 = en1 > 1.f; e1 = s1 ? 0.f : en1;
            uint32_t wv = (s0 ? 0x3F80u : 0u) | (s1 ? 0x3F800000u : 0u);
            asm volatile("st.shared.b32 [%0], %1;"
                :: "r"(sb + OFF_ZBUF + (uint32_t)parW * ZBUF_SZ
                       + (uint32_t)(bl * ZSTR + 256 + qe * 4)), "r"(wv));
        }

        mrow += (size_t)B_TOT * 128;
        HBAR(h);           // per-half barrier: halves run decoupled
    }

    // final: softmax over max voltages (per half)
    if (r256 < 64) {
        float mx = fmaxf(M0, M1);
        float ex0 = expf(M0 - mx), ex1 = expf(M1 - mx);
        float s = ex0 + ex1;
        int b = bgBase + h * 64 + r256;
        out[(size_t)b * 2 + 0] = ex0 / s;
        out[(size_t)b * 2 + 1] = ex1 / s;
    }
}

extern "C" void kernel_launch(void* const* d_in, const int* in_sizes, int n_in,
                              void* d_out, int out_size)
{
    const float* x     = (const float*)d_in[0];
    const float* w_in  = (const float*)d_in[1];
    const float* w_rec = (const float*)d_in[2];
    const float* w_out = (const float*)d_in[3];
    const float* mask  = (const float*)d_in[4];
    float* out = (float*)d_out;

    cudaFuncSetAttribute(snn_hmma_kernel,
                         cudaFuncAttributeMaxDynamicSharedMemorySize, SMEM_BYTES);

    snn_hmma_kernel<<<B_TOT / 128, 512, SMEM_BYTES>>>(x, w_in, w_rec, w_out, mask, out);
}

// round 9
// speedup vs baseline: 1.4144x; 1.1740x over previous
#include <cuda_runtime.h>
#include <cuda_bf16.h>
#include <cstdint>

#define B_TOT    16384
#define TSTEPS   40
#define ZSTR     304                       // bytes/row: 144 bf16 cols + pad (76 words, conflict-free)
#define ZBUF_SZ  (128*ZSTR)                // 38912
#define PLANE_SZ (128*ZSTR)
#define OFF_ZBUF 0                         // 2 buffers (A operand: [z(128) | xs(8) | pad])
#define OFF_WPL  (2*ZBUF_SZ)               // 3 weight split planes [n=128][k=144]
#define OFF_PBUF (OFF_WPL + 3*PLANE_SZ)    // partials [par][half][ng8][64] float2 = 16 KB
#define OFF_WOP  (OFF_PBUF + 16384)        // w_out interleaved pairs: 128 float2 = 1 KB
#define OFF_ZOCC (OFF_WOP + 1024)          // occupancy bytes [par][h][mg][ng8] = 64 B
#define SMEM_BYTES (OFF_ZOCC + 64)

#define HBAR(hh) asm volatile("bar.sync %0, 512;" :: "r"((hh) + 1) : "memory")

__device__ __forceinline__ uint32_t s2u(const void* p) {
    uint32_t a;
    asm("{ .reg .u64 t; cvta.to.shared.u64 t, %1; cvt.u32.u64 %0, t; }" : "=r"(a) : "l"(p));
    return a;
}

__device__ __forceinline__ void ldsm4(uint32_t* r, uint32_t addr) {
    asm volatile("ldmatrix.sync.aligned.m8n8.x4.shared.b16 {%0,%1,%2,%3}, [%4];"
        : "=r"(r[0]), "=r"(r[1]), "=r"(r[2]), "=r"(r[3]) : "r"(addr));
}

__device__ __forceinline__ void mma_bf(float* d, const uint32_t* a, uint32_t b0, uint32_t b1) {
    asm volatile("mma.sync.aligned.m16n8k16.row.col.f32.bf16.bf16.f32 "
        "{%0,%1,%2,%3}, {%4,%5,%6,%7}, {%8,%9}, {%0,%1,%2,%3};"
        : "+f"(d[0]), "+f"(d[1]), "+f"(d[2]), "+f"(d[3])
        : "r"(a[0]), "r"(a[1]), "r"(a[2]), "r"(a[3]), "r"(b0), "r"(b1));
}

__global__ void __launch_bounds__(1024, 1) snn_hmma_kernel(
    const float* __restrict__ x,      // (B,4)
    const float* __restrict__ w_in,   // (128,8)
    const float* __restrict__ w_rec,  // (128,128)
    const float* __restrict__ w_out,  // (2,128)
    const float* __restrict__ mask,   // (T,B,128)
    float* __restrict__ out)          // (B,2)
{
    extern __shared__ char smem[];
    const uint32_t sb = s2u(smem);
    const int tid  = threadIdx.x;
    const int lane = tid & 31, wid = tid >> 5;
    const int h   = wid >> 4;          // half: warps 0-15 -> batches 0-63, 16-31 -> 64-127
    const int mg  = wid & 1;           // M group within half: rows mg*32
    const int ng  = (wid >> 1) & 7;    // N group: cols 16*ng
    const int q   = lane & 3;
    const int rA  = lane >> 2;         // 0..7
    const int rowL = mg * 32 + rA;     // local row within half (+ mt*16 + rh*8)
    const int colBase = ng * 16 + 2 * q;
    const int bgBase  = blockIdx.x * 128;
    const int r512 = tid & 511;        // index within half

    // ---------------- init ----------------
    for (int i = tid; i < 2 * ZBUF_SZ / 4; i += 1024)
        ((uint32_t*)(smem + OFF_ZBUF))[i] = 0u;
    if (tid < 64) smem[OFF_ZOCC + tid] = 0;
    if (tid < 128)
        *(float2*)(smem + OFF_WOP + tid * 8) = make_float2(w_out[tid], w_out[128 + tid]);

    // 3 bf16 split weight planes: plane[s][n][k]; k<128 w_rec, 128..135 w_in, else 0
    for (int idx = tid; idx < 128 * 152; idx += 1024) {
        int n = idx / 152, k = idx % 152;
        float wv = 0.f;
        if (k < 128)       wv = w_rec[n * 128 + k];
        else if (k < 136)  wv = w_in[n * 8 + (k - 128)];
        __nv_bfloat16 b0 = __float2bfloat16(wv);  float r1 = wv - __bfloat162float(b0);
        __nv_bfloat16 b1 = __float2bfloat16(r1);  float r2 = r1 - __bfloat162float(b1);
        __nv_bfloat16 b2 = __float2bfloat16(r2);
        uint32_t o = (uint32_t)(n * ZSTR + k * 2);
        *(__nv_bfloat16*)(smem + OFF_WPL + o)              = b0;
        *(__nv_bfloat16*)(smem + OFF_WPL + PLANE_SZ + o)   = b1;
        *(__nv_bfloat16*)(smem + OFF_WPL + 2*PLANE_SZ + o) = b2;
    }

    // encoder: threads r512<256 of each half own that half's batches (h*64 + r512/4)
    const int bl = h * 64 + (r512 >> 2);       // batch (valid when r512 < 256)
    const int qe = r512 & 3;
    const float esgn = (qe < 2) ? 50.f : -50.f;
    const int   exc  = (qe & 1) * 2;
    float cur0 = 0.f, cur1 = 0.f;
    if (r512 < 256) {
        cur0 = fmaxf(esgn * x[(bgBase + bl) * 4 + exc],     0.f);
        cur1 = fmaxf(esgn * x[(bgBase + bl) * 4 + exc + 1], 0.f);
    }
    float e0 = 0.f, e1 = 0.f;

    __syncthreads();   // zbuf zeroed before encoder writes

    // pre-loop: xs_0 into zbuf[0]
    if (r512 < 256) {
        float en0 = e0 + 0.1f * (cur0 - e0); bool s0 = en0 > 1.f; e0 = s0 ? 0.f : en0;
        float en1 = e1 + 0.1f * (cur1 - e1); bool s1 = en1 > 1.f; e1 = s1 ? 0.f : en1;
        uint32_t wv = (s0 ? 0x3F80u : 0u) | (s1 ? 0x3F800000u : 0u);
        asm volatile("st.shared.b32 [%0], %1;"
            :: "r"(sb + OFF_ZBUF + (uint32_t)(bl * ZSTR + 256 + qe * 4)), "r"(wv));
    }
    __syncthreads();

    // ldmatrix lane addressing
    const uint32_t aLane = (uint32_t)((lane & 15) * ZSTR + (lane >> 4) * 16);
    const uint32_t aBase = sb + OFF_ZBUF + (uint32_t)(h * 64 + mg * 32) * ZSTR + aLane;
    const uint32_t bLane = (uint32_t)((((lane >> 4) & 1) * 8 + (lane & 7)) * ZSTR
                                      + ((lane >> 3) & 1) * 16);
    const uint32_t bBase = sb + OFF_WPL + (uint32_t)(ng * 16) * ZSTR + bLane;

    // state: 32 rows x 16 cols per warp -> 16 c + 16 v per thread
    float v[2][2][4], c[2][2][4];
#pragma unroll
    for (int mt = 0; mt < 2; mt++)
#pragma unroll
        for (int nt = 0; nt < 2; nt++)
#pragma unroll
            for (int d = 0; d < 4; d++) { v[mt][nt][d] = 0.f; c[mt][nt][d] = 0.f; }
    float VO0 = 0.f, VO1 = 0.f, IO0 = 0.f, IO1 = 0.f;
    float M0 = 0.f, M1 = 0.f;      // vo_1 == 0 is a recorded value -> max >= 0

    const float* mrow = mask + (size_t)(bgBase + h * 64 + rowL) * 128 + colBase;

#pragma unroll 1
    for (int t = 0; t < TSTEPS; t++) {
        const int par = t & 1, parW = par ^ 1;

        // (1) LI readout update with p_{t-1}: IO <- io_t, VO <- vo_{t+1}, record
        if (t > 0 && r512 < 64) {
            const char* pb = smem + OFF_PBUF + (size_t)((par ^ 1) * 2 + h) * 4096;
            float s0 = 0.f, s1 = 0.f;
#pragma unroll
            for (int g = 0; g < 8; g++) {
                float2 pv = *(const float2*)(pb + (g * 64 + r512) * 8);
                s0 += pv.x; s1 += pv.y;
            }
            IO0 = IO0 * 0.8f + s0;
            IO1 = IO1 * 0.8f + s1;
            VO0 = VO0 + 0.1f * (IO0 - VO0);
            VO1 = VO1 + 0.1f * (IO1 - VO1);
            M0 = fmaxf(M0, VO0); M1 = fmaxf(M1, VO1);
        }

        // (2) membrane update, spikes z_t
        uint32_t zm = 0;
#pragma unroll
        for (int mt = 0; mt < 2; mt++)
#pragma unroll
            for (int nt = 0; nt < 2; nt++)
#pragma unroll
                for (int d = 0; d < 4; d++) {
                    float vd = v[mt][nt][d] + 0.1f * (c[mt][nt][d] - v[mt][nt][d]);
                    bool z = vd > 1.f;
                    zm |= z ? (1u << (mt * 8 + nt * 4 + d)) : 0u;
                    v[mt][nt][d] = z ? 0.f : vd;
                }

        // (3) write z_t -> zbuf[parW]; occupancy byte; L2 prefetch of needed mask lines
        {
            uint32_t zwBase = sb + OFF_ZBUF + (uint32_t)parW * ZBUF_SZ
                            + (uint32_t)((h * 64 + rowL) * ZSTR + colBase * 2);
#pragma unroll
            for (int mt = 0; mt < 2; mt++)
#pragma unroll
                for (int nt = 0; nt < 2; nt++)
#pragma unroll
                    for (int rh = 0; rh < 2; rh++) {
                        uint32_t bb = (zm >> (mt * 8 + nt * 4 + rh * 2)) & 3u;
                        uint32_t wv = ((bb & 1u) ? 0x3F80u : 0u) | ((bb & 2u) ? 0x3F800000u : 0u);
                        asm volatile("st.shared.b32 [%0], %1;"
                            :: "r"(zwBase + (uint32_t)((mt * 16 + rh * 8) * ZSTR + nt * 16)), "r"(wv));
                    }
            bool any = __any_sync(0xffffffffu, zm != 0u);
            if (lane == 0)
                smem[OFF_ZOCC + parW * 32 + h * 16 + mg * 8 + ng] = any ? 1 : 0;

            if (zm) {
#pragma unroll
                for (int mt = 0; mt < 2; mt++)
#pragma unroll
                    for (int rh = 0; rh < 2; rh++) {
                        uint32_t rb = (zm >> (mt * 8 + rh * 2));
                        if ((rb & 3u) || ((rb >> 4) & 3u)) {
                            const float* pa = mrow + (mt * 16 + rh * 8) * 128;
                            asm volatile("prefetch.global.L2 [%0];" :: "l"(pa));
                            asm volatile("prefetch.global.L2 [%0];" :: "l"(pa + 8));
                        }
                    }
            }
        }

        // (4) c *= 0.8, MMA-accumulate drive
#pragma unroll
        for (int mt = 0; mt < 2; mt++)
#pragma unroll
            for (int nt = 0; nt < 2; nt++)
#pragma unroll
                for (int d = 0; d < 4; d++) c[mt][nt][d] *= 0.8f;

        {
            const uint64_t occ = *(const uint64_t*)(smem + OFF_ZOCC + par * 32 + h * 16 + mg * 8);
            const uint32_t aB = aBase + (uint32_t)par * ZBUF_SZ;
            if (occ != 0ull) {
#pragma unroll
                for (int kt = 0; kt < 8; kt++) {
                    uint32_t a[2][4];
#pragma unroll
                    for (int mt = 0; mt < 2; mt++)
                        ldsm4(a[mt], aB + (uint32_t)(mt * 16 * ZSTR + kt * 32));
#pragma unroll
                    for (int s = 0; s < 3; s++) {
                        uint32_t b[4];
                        ldsm4(b, bBase + (uint32_t)(s * PLANE_SZ + kt * 32));
#pragma unroll
                        for (int mt = 0; mt < 2; mt++) {
                            mma_bf(c[mt][0], a[mt], b[0], b[1]);
                            mma_bf(c[mt][1], a[mt], b[2], b[3]);
                        }
                    }
                }
            }
            {   // kt=8: encoder columns, always
                uint32_t a[2][4];
#pragma unroll
                for (int mt = 0; mt < 2; mt++)
                    ldsm4(a[mt], aB + (uint32_t)(mt * 16 * ZSTR + 8 * 32));
#pragma unroll
                for (int s = 0; s < 3; s++) {
                    uint32_t b[4];
                    ldsm4(b, bBase + (uint32_t)(s * PLANE_SZ + 8 * 32));
#pragma unroll
                    for (int mt = 0; mt < 2; mt++) {
                        mma_bf(c[mt][0], a[mt], b[0], b[1]);
                        mma_bf(c[mt][1], a[mt], b[2], b[3]);
                    }
                }
            }
        }

        // (5) dropout + readout partials p_t -> pbuf[par][h][ng]
        {
            char* pb = smem + OFF_PBUF + (size_t)((par * 2 + h) * 8 + ng) * 512;
#pragma unroll
            for (int mt = 0; mt < 2; mt++)
#pragma unroll
                for (int rh = 0; rh < 2; rh++) {
                    float p0 = 0.f, p1 = 0.f;
                    uint32_t rb = zm >> (mt * 8 + rh * 2);
                    if ((rb & 3u) | ((rb >> 4) & 3u)) {
#pragma unroll
                        for (int nt = 0; nt < 2; nt++) {
                            uint32_t bb = (rb >> (nt * 4)) & 3u;
                            if (bb) {
                                float2 mv = *(const float2*)(mrow + (mt * 16 + rh * 8) * 128 + nt * 8);
                                float4 wp = *(const float4*)(smem + OFF_WOP + (colBase + nt * 8) * 8);
                                if (bb & 1u) { p0 += mv.x * wp.x; p1 += mv.x * wp.y; }
                                if (bb & 2u) { p0 += mv.y * wp.z; p1 += mv.y * wp.w; }
                            }
                        }
                    }
                    p0 += __shfl_xor_sync(0xffffffffu, p0, 1);
                    p0 += __shfl_xor_sync(0xffffffffu, p0, 2);
                    p1 += __shfl_xor_sync(0xffffffffu, p1, 1);
                    p1 += __shfl_xor_sync(0xffffffffu, p1, 2);
                    if (q == 0)
                        *(float2*)(pb + (rowL + mt * 16 + rh * 8) * 8) = make_float2(p0, p1);
                }
        }

        // (6) encoder advance -> xs_{t+1} into zbuf[parW]
        if (r512 < 256) {
            float en0 = e0 + 0.1f * (cur0 - e0); bool s0 = en0 > 1.f; e0 = s0 ? 0.f : en0;
            float en1 = e1 + 0.1f * (cur1 - e1); bool s1 = en1 > 1.f; e1 = s1 ? 0.f : en1;
            uint32_t wv = (s0 ? 0x3F80u : 0u) | (s1 ? 0x3F800000u : 0u);
            asm volatile("st.shared.b32 [%0], %1;"
                :: "r"(sb + OFF_ZBUF + (uint32_t)parW * ZBUF_SZ
                       + (uint32_t)(bl * ZSTR + 256 + qe * 4)), "r"(wv));
        }

        mrow += (size_t)B_TOT * 128;
        HBAR(h);           // per-half barrier: halves run decoupled
    }

    // final: softmax over max recorded voltages (vo_1..vo_40; NO extra LI step)
    if (r512 < 64) {
        float mx = fmaxf(M0, M1);
        float ex0 = expf(M0 - mx), ex1 = expf(M1 - mx);
        float s = ex0 + ex1;
        int b = bgBase + h * 64 + r512;
        out[(size_t)b * 2 + 0] = ex0 / s;
        out[(size_t)b * 2 + 1] = ex1 / s;
    }
}

extern "C" void kernel_launch(void* const* d_in, const int* in_sizes, int n_in,
                              void* d_out, int out_size)
{
    const float* x     = (const float*)d_in[0];
    const float* w_in  = (const float*)d_in[1];
    const float* w_rec = (const float*)d_in[2];
    const float* w_out = (const float*)d_in[3];
    const float* mask  = (const float*)d_in[4];
    float* out = (float*)d_out;

    cudaFuncSetAttribute(snn_hmma_kernel,
                         cudaFuncAttributeMaxDynamicSharedMemorySize, SMEM_BYTES);

    snn_hmma_kernel<<<B_TOT / 128, 1024, SMEM_BYTES>>>(x, w_in, w_rec, w_out, mask, out);
}

// round 10
// speedup vs baseline: 2.1440x; 1.5158x over previous
#include <cuda_runtime.h>
#include <cuda_fp16.h>
#include <cstdint>

#define B_TOT    16384
#define TSTEPS   40
#define ZSTR     272                      // 136 fp16 cols; 68 words % 32 == 4 -> conflict-free ldsm
#define ZBUF_SZ  (64*ZSTR)                // 17408
#define PLANE_SZ (128*ZSTR)               // 34816
#define OFF_ZBUF 0                        // 2 buffers: A operand [z(128) | xs(8)]
#define OFF_WPL  (2*ZBUF_SZ)              // 2 fp16 split planes [n=128][k=136]
#define OFF_PBUF (OFF_WPL + 2*PLANE_SZ)   // partials [par][ng8][64] float2 = 8 KB
#define OFF_WOP  (OFF_PBUF + 8192)        // w_out interleaved pairs (128 float2)
#define OFF_ZOCC (OFF_WOP + 1024)         // occupancy bytes [par][mg][ng8] = 32 B
#define SMEM_BYTES (OFF_ZOCC + 32)        // 113696 B -> 2 CTAs/SM

__device__ __forceinline__ uint32_t s2u(const void* p) {
    uint32_t a;
    asm("{ .reg .u64 t; cvta.to.shared.u64 t, %1; cvt.u32.u64 %0, t; }" : "=r"(a) : "l"(p));
    return a;
}

__device__ __forceinline__ void ldsm4(uint32_t* r, uint32_t addr) {
    asm volatile("ldmatrix.sync.aligned.m8n8.x4.shared.b16 {%0,%1,%2,%3}, [%4];"
        : "=r"(r[0]), "=r"(r[1]), "=r"(r[2]), "=r"(r[3]) : "r"(addr));
}

__device__ __forceinline__ void ldsm2(uint32_t* r, uint32_t addr) {
    asm volatile("ldmatrix.sync.aligned.m8n8.x2.shared.b16 {%0,%1}, [%2];"
        : "=r"(r[0]), "=r"(r[1]) : "r"(addr));
}

__device__ __forceinline__ void mma16(float* d, const uint32_t* a, uint32_t b0, uint32_t b1) {
    asm volatile("mma.sync.aligned.m16n8k16.row.col.f32.f16.f16.f32 "
        "{%0,%1,%2,%3}, {%4,%5,%6,%7}, {%8,%9}, {%0,%1,%2,%3};"
        : "+f"(d[0]), "+f"(d[1]), "+f"(d[2]), "+f"(d[3])
        : "r"(a[0]), "r"(a[1]), "r"(a[2]), "r"(a[3]), "r"(b0), "r"(b1));
}

__device__ __forceinline__ void mma8(float* d, uint32_t a0, uint32_t a1, uint32_t b0) {
    asm volatile("mma.sync.aligned.m16n8k8.row.col.f32.f16.f16.f32 "
        "{%0,%1,%2,%3}, {%4,%5}, {%6}, {%0,%1,%2,%3};"
        : "+f"(d[0]), "+f"(d[1]), "+f"(d[2]), "+f"(d[3])
        : "r"(a0), "r"(a1), "r"(b0));
}

__global__ void __launch_bounds__(512, 2) snn_hmma_kernel(
    const float* __restrict__ x,      // (B,4)
    const float* __restrict__ w_in,   // (128,8)
    const float* __restrict__ w_rec,  // (128,128)
    const float* __restrict__ w_out,  // (2,128)
    const float* __restrict__ mask,   // (T,B,128)
    float* __restrict__ out)          // (B,2)
{
    extern __shared__ char smem[];
    const uint32_t sb = s2u(smem);
    const int tid  = threadIdx.x;
    const int lane = tid & 31, wid = tid >> 5;
    const int mg  = wid & 1;           // rows mg*32 of this CTA's 64
    const int ng  = wid >> 1;          // cols 16*ng
    const int q   = lane & 3;
    const int rA  = lane >> 2;
    const int rowL = mg * 32 + rA;     // + mt*16 + rh*8
    const int colBase = ng * 16 + 2 * q;
    const int bgBase  = blockIdx.x * 64;

    // ---------------- init ----------------
    for (int i = tid; i < 2 * ZBUF_SZ / 4; i += 512)
        ((uint32_t*)(smem + OFF_ZBUF))[i] = 0u;
    if (tid < 32) smem[OFF_ZOCC + tid] = 0;
    if (tid < 128)
        *(float2*)(smem + OFF_WOP + tid * 8) = make_float2(w_out[tid], w_out[128 + tid]);

    // 2 fp16 split planes: [n][k]; k<128 w_rec, 128..135 w_in
    for (int idx = tid; idx < 128 * 136; idx += 512) {
        int n = idx / 136, k = idx - n * 136;
        float wv = (k < 128) ? w_rec[n * 128 + k] : w_in[n * 8 + (k - 128)];
        __half h0 = __float2half_rn(wv);
        float r1 = wv - __half2float(h0);
        __half h1 = __float2half_rn(r1);
        uint32_t o = (uint32_t)(n * ZSTR + k * 2);
        *(__half*)(smem + OFF_WPL + o)            = h0;
        *(__half*)(smem + OFF_WPL + PLANE_SZ + o) = h1;
    }

    // encoder: tid<256 -> batch bl, channels 2*qe, 2*qe+1
    const int bl = tid >> 2;           // 0..63 valid when tid<256
    const int qe = tid & 3;
    const float esgn = (qe < 2) ? 50.f : -50.f;
    const int   exc  = (qe & 1) * 2;
    float cur0 = 0.f, cur1 = 0.f;
    if (tid < 256) {
        cur0 = fmaxf(esgn * x[(bgBase + bl) * 4 + exc],     0.f);
        cur1 = fmaxf(esgn * x[(bgBase + bl) * 4 + exc + 1], 0.f);
    }
    float e0 = 0.f, e1 = 0.f;

    __syncthreads();   // zbuf zeroed before encoder writes

    // pre-loop: xs_0 into zbuf[0] (fp16 ones)
    if (tid < 256) {
        float en0 = e0 + 0.1f * (cur0 - e0); bool s0 = en0 > 1.f; e0 = s0 ? 0.f : en0;
        float en1 = e1 + 0.1f * (cur1 - e1); bool s1 = en1 > 1.f; e1 = s1 ? 0.f : en1;
        uint32_t wv = (s0 ? 0x3C00u : 0u) | (s1 ? 0x3C000000u : 0u);
        asm volatile("st.shared.b32 [%0], %1;"
            :: "r"(sb + OFF_ZBUF + (uint32_t)(bl * ZSTR + 256 + qe * 4)), "r"(wv));
    }
    __syncthreads();

    // ldmatrix addressing
    const uint32_t aLane = (uint32_t)((lane & 15) * ZSTR + (lane >> 4) * 16);
    const uint32_t aBase = sb + OFF_ZBUF + (uint32_t)(mg * 32) * ZSTR + aLane;
    const uint32_t bLane = (uint32_t)((((lane >> 4) & 1) * 8 + (lane & 7)) * ZSTR
                                      + ((lane >> 3) & 1) * 16);
    const uint32_t bBase = sb + OFF_WPL + (uint32_t)(ng * 16) * ZSTR + bLane;
    // k8 tail addressing (lanes 0-15 meaningful)
    const uint32_t tRow  = (uint32_t)((lane & 15) * ZSTR);
    const uint32_t aTail0 = sb + OFF_ZBUF + (uint32_t)(mg * 32) * ZSTR + tRow + 256;
    const uint32_t bTail0 = sb + OFF_WPL + (uint32_t)(ng * 16) * ZSTR + tRow + 256;

    // state: 32 rows x 16 cols per warp
    float v[2][2][4], c[2][2][4];
#pragma unroll
    for (int mt = 0; mt < 2; mt++)
#pragma unroll
        for (int nt = 0; nt < 2; nt++)
#pragma unroll
            for (int d = 0; d < 4; d++) { v[mt][nt][d] = 0.f; c[mt][nt][d] = 0.f; }
    float VO0 = 0.f, VO1 = 0.f, IO0 = 0.f, IO1 = 0.f;
    float M0 = 0.f, M1 = 0.f;          // vo_1 == 0 is a recorded value

    const float* mrow = mask + (size_t)(bgBase + rowL) * 128 + colBase;

    // prefetch step-0 mask lines
#pragma unroll
    for (int mt = 0; mt < 2; mt++)
#pragma unroll
        for (int rh = 0; rh < 2; rh++)
            asm volatile("prefetch.global.L2 [%0];" :: "l"(mrow + (mt * 16 + rh * 8) * 128));

#pragma unroll 1
    for (int t = 0; t < TSTEPS; t++) {
        const int par = t & 1, parW = par ^ 1;

        // (1) LI readout update with p_{t-1}
        if (t > 0 && tid < 64) {
            const char* pb = smem + OFF_PBUF + (size_t)(par ^ 1) * 4096;
            float s0 = 0.f, s1 = 0.f;
#pragma unroll
            for (int g = 0; g < 8; g++) {
                float2 pv = *(const float2*)(pb + (g * 64 + tid) * 8);
                s0 += pv.x; s1 += pv.y;
            }
            IO0 = IO0 * 0.8f + s0;
            IO1 = IO1 * 0.8f + s1;
            VO0 = VO0 + 0.1f * (IO0 - VO0);
            VO1 = VO1 + 0.1f * (IO1 - VO1);
            M0 = fmaxf(M0, VO0); M1 = fmaxf(M1, VO1);
        }

        // (2) membrane update, spikes z_t
        uint32_t zm = 0;
#pragma unroll
        for (int mt = 0; mt < 2; mt++)
#pragma unroll
            for (int nt = 0; nt < 2; nt++)
#pragma unroll
                for (int d = 0; d < 4; d++) {
                    float vd = v[mt][nt][d] + 0.1f * (c[mt][nt][d] - v[mt][nt][d]);
                    bool z = vd > 1.f;
                    zm |= z ? (1u << (mt * 8 + nt * 4 + d)) : 0u;
                    v[mt][nt][d] = z ? 0.f : vd;
                }

        // (3) write z_t (fp16) -> zbuf[parW]; occupancy byte
        {
            uint32_t zwBase = sb + OFF_ZBUF + (uint32_t)parW * ZBUF_SZ
                            + (uint32_t)(rowL * ZSTR + colBase * 2);
#pragma unroll
            for (int mt = 0; mt < 2; mt++)
#pragma unroll
                for (int nt = 0; nt < 2; nt++)
#pragma unroll
                    for (int rh = 0; rh < 2; rh++) {
                        uint32_t bb = (zm >> (mt * 8 + nt * 4 + rh * 2)) & 3u;
                        uint32_t wv = ((bb & 1u) ? 0x3C00u : 0u) | ((bb & 2u) ? 0x3C000000u : 0u);
                        asm volatile("st.shared.b32 [%0], %1;"
                            :: "r"(zwBase + (uint32_t)((mt * 16 + rh * 8) * ZSTR + nt * 16)), "r"(wv));
                    }
            bool any = __any_sync(0xffffffffu, zm != 0u);
            if (lane == 0)
                smem[OFF_ZOCC + parW * 16 + mg * 8 + ng] = any ? 1 : 0;
        }

        // (3.5) dropout + readout partials (branchless, unconditional dense loads)
        {
            char* pb = smem + OFF_PBUF + (size_t)par * 4096;
#pragma unroll
            for (int mt = 0; mt < 2; mt++) {
                float2 mv[4];
#pragma unroll
                for (int rh = 0; rh < 2; rh++)
#pragma unroll
                    for (int nt = 0; nt < 2; nt++)
                        mv[rh * 2 + nt] = *(const float2*)(mrow + (mt * 16 + rh * 8) * 128 + nt * 8);
#pragma unroll
                for (int rh = 0; rh < 2; rh++) {
                    float p0 = 0.f, p1 = 0.f;
                    uint32_t rb = zm >> (mt * 8 + rh * 2);
#pragma unroll
                    for (int nt = 0; nt < 2; nt++) {
                        uint32_t bb = (rb >> (nt * 4)) & 3u;
                        float4 wp = *(const float4*)(smem + OFF_WOP + (colBase + nt * 8) * 8);
                        float gx = (bb & 1u) ? mv[rh * 2 + nt].x : 0.f;
                        float gy = (bb & 2u) ? mv[rh * 2 + nt].y : 0.f;
                        p0 += gx * wp.x + gy * wp.z;
                        p1 += gx * wp.y + gy * wp.w;
                    }
                    p0 += __shfl_xor_sync(0xffffffffu, p0, 1);
                    p0 += __shfl_xor_sync(0xffffffffu, p0, 2);
                    p1 += __shfl_xor_sync(0xffffffffu, p1, 1);
                    p1 += __shfl_xor_sync(0xffffffffu, p1, 2);
                    if (q == 0)
                        *(float2*)(pb + (ng * 64 + rowL + mt * 16 + rh * 8) * 8)
                            = make_float2(p0, p1);
                }
            }
        }

        // (4) c *= 0.8, MMA-accumulate drive = [z_{t-1}|xs_t] @ (plane0 + plane1)
#pragma unroll
        for (int mt = 0; mt < 2; mt++)
#pragma unroll
            for (int nt = 0; nt < 2; nt++)
#pragma unroll
                for (int d = 0; d < 4; d++) c[mt][nt][d] *= 0.8f;

        {
            const uint64_t occ = *(const uint64_t*)(smem + OFF_ZOCC + par * 16 + mg * 8);
            const uint32_t aB = aBase + (uint32_t)par * ZBUF_SZ;
            if (occ != 0ull) {
#pragma unroll
                for (int kt = 0; kt < 8; kt++) {
                    uint32_t a[2][4];
#pragma unroll
                    for (int mt = 0; mt < 2; mt++)
                        ldsm4(a[mt], aB + (uint32_t)(mt * 16 * ZSTR + kt * 32));
#pragma unroll
                    for (int s = 0; s < 2; s++) {
                        uint32_t b[4];
                        ldsm4(b, bBase + (uint32_t)(s * PLANE_SZ + kt * 32));
#pragma unroll
                        for (int mt = 0; mt < 2; mt++) {
                            mma16(c[mt][0], a[mt], b[0], b[1]);
                            mma16(c[mt][1], a[mt], b[2], b[3]);
                        }
                    }
                }
            }
            {   // k8 tail: encoder columns 128..135, always
                uint32_t at[2][2];
#pragma unroll
                for (int mt = 0; mt < 2; mt++)
                    ldsm2(at[mt], aTail0 + (uint32_t)par * ZBUF_SZ + (uint32_t)(mt * 16 * ZSTR));
#pragma unroll
                for (int s = 0; s < 2; s++) {
                    uint32_t bt[2];
                    ldsm2(bt, bTail0 + (uint32_t)(s * PLANE_SZ));
#pragma unroll
                    for (int mt = 0; mt < 2; mt++) {
                        mma8(c[mt][0], at[mt][0], at[mt][1], bt[0]);
                        mma8(c[mt][1], at[mt][0], at[mt][1], bt[1]);
                    }
                }
            }
        }

        // prefetch next step's mask lines (hides DRAM->L2 behind this step's tail)
        if (t < TSTEPS - 1) {
            const float* nrow = mrow + (size_t)B_TOT * 128;
#pragma unroll
            for (int mt = 0; mt < 2; mt++)
#pragma unroll
                for (int rh = 0; rh < 2; rh++)
                    asm volatile("prefetch.global.L2 [%0];"
                                 :: "l"(nrow + (mt * 16 + rh * 8) * 128));
        }

        // (6) encoder advance -> xs_{t+1} into zbuf[parW]
        if (tid < 256) {
            float en0 = e0 + 0.1f * (cur0 - e0); bool s0 = en0 > 1.f; e0 = s0 ? 0.f : en0;
            float en1 = e1 + 0.1f * (cur1 - e1); bool s1 = en1 > 1.f; e1 = s1 ? 0.f : en1;
            uint32_t wv = (s0 ? 0x3C00u : 0u) | (s1 ? 0x3C000000u : 0u);
            asm volatile("st.shared.b32 [%0], %1;"
                :: "r"(sb + OFF_ZBUF + (uint32_t)parW * ZBUF_SZ
                       + (uint32_t)(bl * ZSTR + 256 + qe * 4)), "r"(wv));
        }

        mrow += (size_t)B_TOT * 128;
        __syncthreads();
    }

    // final: softmax over max recorded voltages (vo_1..vo_40)
    if (tid < 64) {
        float mx = fmaxf(M0, M1);
        float ex0 = expf(M0 - mx), ex1 = expf(M1 - mx);
        float s = ex0 + ex1;
        int b = bgBase + tid;
        out[(size_t)b * 2 + 0] = ex0 / s;
        out[(size_t)b * 2 + 1] = ex1 / s;
    }
}

extern "C" void kernel_launch(void* const* d_in, const int* in_sizes, int n_in,
                              void* d_out, int out_size)
{
    const float* x     = (const float*)d_in[0];
    const float* w_in  = (const float*)d_in[1];
    const float* w_rec = (const float*)d_in[2];
    const float* w_out = (const float*)d_in[3];
    const float* mask  = (const float*)d_in[4];
    float* out = (float*)d_out;

    cudaFuncSetAttribute(snn_hmma_kernel,
                         cudaFuncAttributeMaxDynamicSharedMemorySize, SMEM_BYTES);

    snn_hmma_kernel<<<B_TOT / 64, 512, SMEM_BYTES>>>(x, w_in, w_rec, w_out, mask, out);
}

// round 11
// speedup vs baseline: 2.1624x; 1.0086x over previous
#include <cuda_runtime.h>
#include <cuda_fp16.h>
#include <cstdint>

#define B_TOT    16384
#define TSTEPS   40
#define ZSTR     272                      // 136 fp16 cols; 68 words % 32 == 4 -> conflict-free ldsm
#define ZBUF_SZ  (64*ZSTR)                // 17408
#define PLANE_SZ (128*ZSTR)               // 34816
#define OFF_ZBUF 0                        // 2 buffers: A operand [z(128) | xs(8)]
#define OFF_WPL  (2*ZBUF_SZ)              // 2 fp16 split planes [n=128][k=136]
#define OFF_PBUF (OFF_WPL + 2*PLANE_SZ)   // partials [par][ng8][64] float2 = 8 KB
#define OFF_WOP  (OFF_PBUF + 8192)        // w_out interleaved pairs (128 float2)
#define OFF_ZOCC (OFF_WOP + 1024)         // occupancy bytes [par][mg][ng8] = 32 B
#define SMEM_BYTES (OFF_ZOCC + 32)        // 113696 B -> 2 CTAs/SM

// per-mg-group barrier: 8 warps = 256 threads, ids 1 and 2
#define HBAR(g) asm volatile("bar.sync %0, 256;" :: "r"((g) + 1) : "memory")

__device__ __forceinline__ uint32_t s2u(const void* p) {
    uint32_t a;
    asm("{ .reg .u64 t; cvta.to.shared.u64 t, %1; cvt.u32.u64 %0, t; }" : "=r"(a) : "l"(p));
    return a;
}

__device__ __forceinline__ void ldsm4(uint32_t* r, uint32_t addr) {
    asm volatile("ldmatrix.sync.aligned.m8n8.x4.shared.b16 {%0,%1,%2,%3}, [%4];"
        : "=r"(r[0]), "=r"(r[1]), "=r"(r[2]), "=r"(r[3]) : "r"(addr));
}

__device__ __forceinline__ void ldsm2(uint32_t* r, uint32_t addr) {
    asm volatile("ldmatrix.sync.aligned.m8n8.x2.shared.b16 {%0,%1}, [%2];"
        : "=r"(r[0]), "=r"(r[1]) : "r"(addr));
}

__device__ __forceinline__ void mma16(float* d, const uint32_t* a, uint32_t b0, uint32_t b1) {
    asm volatile("mma.sync.aligned.m16n8k16.row.col.f32.f16.f16.f32 "
        "{%0,%1,%2,%3}, {%4,%5,%6,%7}, {%8,%9}, {%0,%1,%2,%3};"
        : "+f"(d[0]), "+f"(d[1]), "+f"(d[2]), "+f"(d[3])
        : "r"(a[0]), "r"(a[1]), "r"(a[2]), "r"(a[3]), "r"(b0), "r"(b1));
}

__device__ __forceinline__ void mma8(float* d, uint32_t a0, uint32_t a1, uint32_t b0) {
    asm volatile("mma.sync.aligned.m16n8k8.row.col.f32.f16.f16.f32 "
        "{%0,%1,%2,%3}, {%4,%5}, {%6}, {%0,%1,%2,%3};"
        : "+f"(d[0]), "+f"(d[1]), "+f"(d[2]), "+f"(d[3])
        : "r"(a0), "r"(a1), "r"(b0));
}

__global__ void __launch_bounds__(512, 2) snn_hmma_kernel(
    const float* __restrict__ x,      // (B,4)
    const float* __restrict__ w_in,   // (128,8)
    const float* __restrict__ w_rec,  // (128,128)
    const float* __restrict__ w_out,  // (2,128)
    const float* __restrict__ mask,   // (T,B,128)
    float* __restrict__ out)          // (B,2)
{
    extern __shared__ char smem[];
    const uint32_t sb = s2u(smem);
    const int tid  = threadIdx.x;
    const int lane = tid & 31, wid = tid >> 5;
    const int mg  = wid & 1;           // rows mg*32 of this CTA's 64
    const int ng  = wid >> 1;          // cols 16*ng
    const int q   = lane & 3;
    const int rA  = lane >> 2;
    const int rowL = mg * 32 + rA;     // + mt*16 + rh*8
    const int colBase = ng * 16 + 2 * q;
    const int bgBase  = blockIdx.x * 64;

    // ---------------- init ----------------
    for (int i = tid; i < 2 * ZBUF_SZ / 4; i += 512)
        ((uint32_t*)(smem + OFF_ZBUF))[i] = 0u;
    if (tid < 32) smem[OFF_ZOCC + tid] = 0;
    if (tid < 128)
        *(float2*)(smem + OFF_WOP + tid * 8) = make_float2(w_out[tid], w_out[128 + tid]);

    // 2 fp16 split planes: [n][k]; k<128 w_rec, 128..135 w_in
    for (int idx = tid; idx < 128 * 136; idx += 512) {
        int n = idx / 136, k = idx - n * 136;
        float wv = (k < 128) ? w_rec[n * 128 + k] : w_in[n * 8 + (k - 128)];
        __half h0 = __float2half_rn(wv);
        float r1 = wv - __half2float(h0);
        __half h1 = __float2half_rn(r1);
        uint32_t o = (uint32_t)(n * ZSTR + k * 2);
        *(__half*)(smem + OFF_WPL + o)            = h0;
        *(__half*)(smem + OFF_WPL + PLANE_SZ + o) = h1;
    }

    // encoder ownership remapped mg-local: warp (mg, e=wid>>1) lanes 0-15
    // handle batches mg*32 + e*4 + (lane>>2), channel pair qe = lane&3.
    const int eb = mg * 32 + (wid >> 1) * 4 + (lane >> 2);   // batch (lane<16)
    const int qe = lane & 3;
    const float esgn = (qe < 2) ? 50.f : -50.f;
    const int   exc  = (qe & 1) * 2;
    float cur0 = 0.f, cur1 = 0.f;
    if (lane < 16) {
        cur0 = fmaxf(esgn * x[(bgBase + eb) * 4 + exc],     0.f);
        cur1 = fmaxf(esgn * x[(bgBase + eb) * 4 + exc + 1], 0.f);
    }
    float e0 = 0.f, e1 = 0.f;
    const uint32_t encAddr = sb + OFF_ZBUF + (uint32_t)(eb * ZSTR + 256 + qe * 4);

    __syncthreads();   // full barrier: init complete

    // pre-loop: xs_0 into zbuf[0] (fp16 ones)
    if (lane < 16) {
        float en0 = e0 + 0.1f * (cur0 - e0); bool s0 = en0 > 1.f; e0 = s0 ? 0.f : en0;
        float en1 = e1 + 0.1f * (cur1 - e1); bool s1 = en1 > 1.f; e1 = s1 ? 0.f : en1;
        uint32_t wv = (s0 ? 0x3C00u : 0u) | (s1 ? 0x3C000000u : 0u);
        asm volatile("st.shared.b32 [%0], %1;" :: "r"(encAddr), "r"(wv));
    }
    __syncthreads();

    // ldmatrix addressing
    const uint32_t aLane = (uint32_t)((lane & 15) * ZSTR + (lane >> 4) * 16);
    const uint32_t aBase = sb + OFF_ZBUF + (uint32_t)(mg * 32) * ZSTR + aLane;
    const uint32_t bLane = (uint32_t)((((lane >> 4) & 1) * 8 + (lane & 7)) * ZSTR
                                      + ((lane >> 3) & 1) * 16);
    const uint32_t bBase = sb + OFF_WPL + (uint32_t)(ng * 16) * ZSTR + bLane;
    const uint32_t tRow  = (uint32_t)((lane & 15) * ZSTR);
    const uint32_t aTail0 = sb + OFF_ZBUF + (uint32_t)(mg * 32) * ZSTR + tRow + 256;
    const uint32_t bTail0 = sb + OFF_WPL + (uint32_t)(ng * 16) * ZSTR + tRow + 256;

    // state: 32 rows x 16 cols per warp
    float v[2][2][4], c[2][2][4];
#pragma unroll
    for (int mt = 0; mt < 2; mt++)
#pragma unroll
        for (int nt = 0; nt < 2; nt++)
#pragma unroll
            for (int d = 0; d < 4; d++) { v[mt][nt][d] = 0.f; c[mt][nt][d] = 0.f; }
    float VO0 = 0.f, VO1 = 0.f, IO0 = 0.f, IO1 = 0.f;
    float M0 = 0.f, M1 = 0.f;          // vo_1 == 0 is a recorded value

    const float* mrow = mask + (size_t)(bgBase + rowL) * 128 + colBase;

    // prefetch step-0 mask lines (one lane per row-line)
    if (q == 0) {
#pragma unroll
        for (int mt = 0; mt < 2; mt++)
#pragma unroll
            for (int rh = 0; rh < 2; rh++)
                asm volatile("prefetch.global.L2 [%0];" :: "l"(mrow + (mt * 16 + rh * 8) * 128));
    }

#pragma unroll 1
    for (int t = 0; t < TSTEPS - 1; t++) {      // step 39 is epilogue-only
        const int par = t & 1, parW = par ^ 1;

        // (0) mask loads issued at step top (consumed in 3.5; L2-hot via prefetch)
        float2 mv[8];
#pragma unroll
        for (int mt = 0; mt < 2; mt++)
#pragma unroll
            for (int rh = 0; rh < 2; rh++)
#pragma unroll
                for (int nt = 0; nt < 2; nt++)
                    mv[mt * 4 + rh * 2 + nt] =
                        *(const float2*)(mrow + (mt * 16 + rh * 8) * 128 + nt * 8);

        // (1) LI readout update with p_{t-1}
        if (t > 0 && tid < 64) {
            const char* pb = smem + OFF_PBUF + (size_t)(par ^ 1) * 4096;
            float s0 = 0.f, s1 = 0.f;
#pragma unroll
            for (int g = 0; g < 8; g++) {
                float2 pv = *(const float2*)(pb + (g * 64 + tid) * 8);
                s0 += pv.x; s1 += pv.y;
            }
            IO0 = IO0 * 0.8f + s0;
            IO1 = IO1 * 0.8f + s1;
            VO0 = VO0 + 0.1f * (IO0 - VO0);
            VO1 = VO1 + 0.1f * (IO1 - VO1);
            M0 = fmaxf(M0, VO0); M1 = fmaxf(M1, VO1);
        }

        // (2) membrane update, spikes z_t
        uint32_t zm = 0;
#pragma unroll
        for (int mt = 0; mt < 2; mt++)
#pragma unroll
            for (int nt = 0; nt < 2; nt++)
#pragma unroll
                for (int d = 0; d < 4; d++) {
                    float vd = v[mt][nt][d] + 0.1f * (c[mt][nt][d] - v[mt][nt][d]);
                    bool z = vd > 1.f;
                    zm |= z ? (1u << (mt * 8 + nt * 4 + d)) : 0u;
                    v[mt][nt][d] = z ? 0.f : vd;
                }

        // (3) write z_t (fp16) -> zbuf[parW]; occupancy byte
        {
            uint32_t zwBase = sb + OFF_ZBUF + (uint32_t)parW * ZBUF_SZ
                            + (uint32_t)(rowL * ZSTR + colBase * 2);
#pragma unroll
            for (int mt = 0; mt < 2; mt++)
#pragma unroll
                for (int nt = 0; nt < 2; nt++)
#pragma unroll
                    for (int rh = 0; rh < 2; rh++) {
                        uint32_t bb = (zm >> (mt * 8 + nt * 4 + rh * 2)) & 3u;
                        uint32_t wv = ((bb & 1u) ? 0x3C00u : 0u) | ((bb & 2u) ? 0x3C000000u : 0u);
                        asm volatile("st.shared.b32 [%0], %1;"
                            :: "r"(zwBase + (uint32_t)((mt * 16 + rh * 8) * ZSTR + nt * 16)), "r"(wv));
                    }
            bool any = __any_sync(0xffffffffu, zm != 0u);
            if (lane == 0)
                smem[OFF_ZOCC + parW * 16 + mg * 8 + ng] = any ? 1 : 0;
        }

        // (3.5) dropout + readout partials -> pbuf[par] (consumes mv)
        {
            char* pb = smem + OFF_PBUF + (size_t)par * 4096;
#pragma unroll
            for (int mt = 0; mt < 2; mt++)
#pragma unroll
                for (int rh = 0; rh < 2; rh++) {
                    float p0 = 0.f, p1 = 0.f;
                    uint32_t rb = zm >> (mt * 8 + rh * 2);
#pragma unroll
                    for (int nt = 0; nt < 2; nt++) {
                        uint32_t bb = (rb >> (nt * 4)) & 3u;
                        float4 wp = *(const float4*)(smem + OFF_WOP + (colBase + nt * 8) * 8);
                        float gx = (bb & 1u) ? mv[mt * 4 + rh * 2 + nt].x : 0.f;
                        float gy = (bb & 2u) ? mv[mt * 4 + rh * 2 + nt].y : 0.f;
                        p0 += gx * wp.x + gy * wp.z;
                        p1 += gx * wp.y + gy * wp.w;
                    }
                    p0 += __shfl_xor_sync(0xffffffffu, p0, 1);
                    p0 += __shfl_xor_sync(0xffffffffu, p0, 2);
                    p1 += __shfl_xor_sync(0xffffffffu, p1, 1);
                    p1 += __shfl_xor_sync(0xffffffffu, p1, 2);
                    if (q == 0)
                        *(float2*)(pb + (ng * 64 + rowL + mt * 16 + rh * 8) * 8)
                            = make_float2(p0, p1);
                }
        }

        // (6) encoder advance -> xs_{t+1} into zbuf[parW]
        if (lane < 16) {
            float en0 = e0 + 0.1f * (cur0 - e0); bool s0 = en0 > 1.f; e0 = s0 ? 0.f : en0;
            float en1 = e1 + 0.1f * (cur1 - e1); bool s1 = en1 > 1.f; e1 = s1 ? 0.f : en1;
            uint32_t wv = (s0 ? 0x3C00u : 0u) | (s1 ? 0x3C000000u : 0u);
            asm volatile("st.shared.b32 [%0], %1;"
                :: "r"(encAddr + (uint32_t)parW * ZBUF_SZ), "r"(wv));
        }

        // prefetch next step's mask lines
        if (q == 0) {
            const float* nrow = mrow + (size_t)B_TOT * 128;
#pragma unroll
            for (int mt = 0; mt < 2; mt++)
#pragma unroll
                for (int rh = 0; rh < 2; rh++)
                    asm volatile("prefetch.global.L2 [%0];"
                                 :: "l"(nrow + (mt * 16 + rh * 8) * 128));
        }

        // (4) LAST: c *= 0.8, MMA-accumulate drive = [z_{t-1}|xs_t] @ planes.
        // All smem writes are done above, so the barrier follows immediately and
        // HMMA execution overlaps the next step's front phases.
#pragma unroll
        for (int mt = 0; mt < 2; mt++)
#pragma unroll
            for (int nt = 0; nt < 2; nt++)
#pragma unroll
                for (int d = 0; d < 4; d++) c[mt][nt][d] *= 0.8f;

        {
            const uint64_t occ = *(const uint64_t*)(smem + OFF_ZOCC + par * 16 + mg * 8);
            const uint32_t aB = aBase + (uint32_t)par * ZBUF_SZ;
            if (occ != 0ull) {
#pragma unroll
                for (int kt = 0; kt < 8; kt++) {
                    uint32_t a[2][4];
#pragma unroll
                    for (int mt = 0; mt < 2; mt++)
                        ldsm4(a[mt], aB + (uint32_t)(mt * 16 * ZSTR + kt * 32));
#pragma unroll
                    for (int s = 0; s < 2; s++) {
                        uint32_t b[4];
                        ldsm4(b, bBase + (uint32_t)(s * PLANE_SZ + kt * 32));
#pragma unroll
                        for (int mt = 0; mt < 2; mt++) {
                            mma16(c[mt][0], a[mt], b[0], b[1]);
                            mma16(c[mt][1], a[mt], b[2], b[3]);
                        }
                    }
                }
            }
            {   // k8 tail: encoder columns 128..135, always
                uint32_t at[2][2];
#pragma unroll
                for (int mt = 0; mt < 2; mt++)
                    ldsm2(at[mt], aTail0 + (uint32_t)par * ZBUF_SZ + (uint32_t)(mt * 16 * ZSTR));
#pragma unroll
                for (int s = 0; s < 2; s++) {
                    uint32_t bt[2];
                    ldsm2(bt, bTail0 + (uint32_t)(s * PLANE_SZ));
#pragma unroll
                    for (int mt = 0; mt < 2; mt++) {
                        mma8(c[mt][0], at[mt][0], at[mt][1], bt[0]);
                        mma8(c[mt][1], at[mt][0], at[mt][1], bt[1]);
                    }
                }
            }
        }

        mrow += (size_t)B_TOT * 128;
        HBAR(mg);          // per-mg-group barrier (z/xs/occ/pbuf rows are mg-local)
    }

    // epilogue = step 39's only live work: final LI update with p_38, then softmax
    if (tid < 64) {
        const char* pb = smem + OFF_PBUF + (size_t)(((TSTEPS - 1) & 1) ^ 1) * 4096;
        float s0 = 0.f, s1 = 0.f;
#pragma unroll
        for (int g = 0; g < 8; g++) {
            float2 pv = *(const float2*)(pb + (g * 64 + tid) * 8);
            s0 += pv.x; s1 += pv.y;
        }
        IO0 = IO0 * 0.8f + s0;
        IO1 = IO1 * 0.8f + s1;
        VO0 = VO0 + 0.1f * (IO0 - VO0);
        VO1 = VO1 + 0.1f * (IO1 - VO1);
        M0 = fmaxf(M0, VO0); M1 = fmaxf(M1, VO1);

        float mx = fmaxf(M0, M1);
        float ex0 = expf(M0 - mx), ex1 = expf(M1 - mx);
        float s = ex0 + ex1;
        int b = bgBase + tid;
        out[(size_t)b * 2 + 0] = ex0 / s;
        out[(size_t)b * 2 + 1] = ex1 / s;
    }
}

extern "C" void kernel_launch(void* const* d_in, const int* in_sizes, int n_in,
                              void* d_out, int out_size)
{
    const float* x     = (const float*)d_in[0];
    const float* w_in  = (const float*)d_in[1];
    const float* w_rec = (const float*)d_in[2];
    const float* w_out = (const float*)d_in[3];
    const float* mask  = (const float*)d_in[4];
    float* out = (float*)d_out;

    cudaFuncSetAttribute(snn_hmma_kernel,
                         cudaFuncAttributeMaxDynamicSharedMemorySize, SMEM_BYTES);

    snn_hmma_kernel<<<B_TOT / 64, 512, SMEM_BYTES>>>(x, w_in, w_rec, w_out, mask, out);
}